// round 7
// baseline (speedup 1.0000x reference)
#include <cuda_runtime.h>
#include <math.h>
#include <stdint.h>

#define BB 2
#define SS 2048
#define DD 1024
#define HH 16
#define HD 64

// -------- scratch (allocation-free: __device__ globals) --------
__device__ float g_Q[BB*SS*DD];
__device__ float g_K[BB*SS*DD];
__device__ float g_V[BB*SS*DD];
__device__ float g_att[BB*SS*DD];
// tf32-rounded copies of inputs/weights
__device__ float g_qc[BB*SS*DD];
__device__ float g_kc[BB*SS*DD];
__device__ float g_vc[BB*SS*DD];
__device__ float g_Wq[DD*DD];
__device__ float g_Wk[DD*DD];
__device__ float g_Wv[DD*DD];
__device__ float g_Wo[DD*DD];

// -------- helpers --------
__device__ __forceinline__ uint32_t f2tf32(float x) {
    uint32_t r;
    asm("cvt.rna.tf32.f32 %0, %1;" : "=r"(r) : "f"(x));
    return r;
}

__device__ __forceinline__ void mma_tf32(float* d, const uint32_t* a, const uint32_t* b) {
    asm volatile(
        "mma.sync.aligned.m16n8k8.row.col.f32.tf32.tf32.f32 "
        "{%0,%1,%2,%3},{%4,%5,%6,%7},{%8,%9},{%0,%1,%2,%3};"
        : "+f"(d[0]), "+f"(d[1]), "+f"(d[2]), "+f"(d[3])
        : "r"(a[0]), "r"(a[1]), "r"(a[2]), "r"(a[3]), "r"(b[0]), "r"(b[1]));
}

__device__ __forceinline__ void cp_async16(uint32_t smem_addr, const void* gptr) {
    asm volatile("cp.async.cg.shared.global [%0], [%1], 16;"
                 :: "r"(smem_addr), "l"(gptr));
}
__device__ __forceinline__ void cp_commit() {
    asm volatile("cp.async.commit_group;");
}
template <int N>
__device__ __forceinline__ void cp_wait() {
    asm volatile("cp.async.wait_group %0;" :: "n"(N));
}

// ======================================================================
// Elementwise tf32 rounding pass (run once per launch on inputs/weights)
// ======================================================================
__global__ __launch_bounds__(256) void cvt_tf32_kernel(
    const float* __restrict__ in, float* __restrict__ out, int n4)
{
    int i = blockIdx.x * blockDim.x + threadIdx.x;
    if (i < n4) {
        float4 v = ((const float4*)in)[i];
        uint4 u = { f2tf32(v.x), f2tf32(v.y), f2tf32(v.z), f2tf32(v.w) };
        ((uint4*)out)[i] = u;
    }
}

// ======================================================================
// GEMM: C[M,N] = A[M,K] * B[N,K]^T (+ bias), tf32 tensor core.
// Inputs already tf32-rounded -> no cvt in the loop.
// block 128M x 256N, 256 threads (8 warps, 2Mx4N), warp tile 64x64, KT=32
// cp.async double-buffered. round_out: tf32-round outputs (scratch tensors).
// ======================================================================
#define G_SMEM_BYTES ((2*128*36 + 2*256*36) * 4)

__global__ __launch_bounds__(256) void gemm_tf32_v3(
    const float* __restrict__ A, const float* __restrict__ Bw,
    const float* __restrict__ bias, float* __restrict__ C,
    int M, int N, int K, int round_out)
{
    extern __shared__ float gsm[];
    float* As = gsm;                 // [2][128*36]
    float* Bs = gsm + 2 * 128 * 36;  // [2][256*36]

    const int tid  = threadIdx.x;
    const int lane = tid & 31;
    const int w    = tid >> 5;
    const int wm   = w & 1;
    const int wn   = w >> 1;
    const int lr   = lane >> 2;
    const int lc   = lane & 3;

    const int m0 = blockIdx.y * 128;
    const int n0 = blockIdx.x * 256;

    const uint32_t as_base = (uint32_t)__cvta_generic_to_shared(As);
    const uint32_t bs_base = (uint32_t)__cvta_generic_to_shared(Bs);

    auto load_stage = [&](int s, int kt) {
        #pragma unroll
        for (int i = 0; i < 4; i++) {
            int id = tid + i * 256;
            int r = id >> 3, c = (id & 7) * 4;
            cp_async16(as_base + (s * 128 * 36 + r * 36 + c) * 4,
                       &A[(size_t)(m0 + r) * K + kt + c]);
        }
        #pragma unroll
        for (int i = 0; i < 8; i++) {
            int id = tid + i * 256;
            int r = id >> 3, c = (id & 7) * 4;
            cp_async16(bs_base + (s * 256 * 36 + r * 36 + c) * 4,
                       &Bw[(size_t)(n0 + r) * K + kt + c]);
        }
        cp_commit();
    };

    float acc[4][8][4];
    #pragma unroll
    for (int i = 0; i < 4; i++)
        #pragma unroll
        for (int j = 0; j < 8; j++)
            #pragma unroll
            for (int t = 0; t < 4; t++) acc[i][j][t] = 0.0f;

    load_stage(0, 0);

    int st = 0;
    for (int kt = 0; kt < K; kt += 32, st ^= 1) {
        if (kt + 32 < K) { load_stage(st ^ 1, kt + 32); cp_wait<1>(); }
        else             { cp_wait<0>(); }
        __syncthreads();

        const float* Ac = As + st * 128 * 36;
        const float* Bc = Bs + st * 256 * 36;

        #pragma unroll
        for (int ks = 0; ks < 4; ks++) {
            const int kk = ks * 8;
            uint32_t af[4][4];
            #pragma unroll
            for (int mf = 0; mf < 4; mf++) {
                int r = wm * 64 + mf * 16 + lr;
                af[mf][0] = __float_as_uint(Ac[r * 36 + kk + lc]);
                af[mf][1] = __float_as_uint(Ac[(r + 8) * 36 + kk + lc]);
                af[mf][2] = __float_as_uint(Ac[r * 36 + kk + lc + 4]);
                af[mf][3] = __float_as_uint(Ac[(r + 8) * 36 + kk + lc + 4]);
            }
            uint32_t bf[8][2];
            #pragma unroll
            for (int nf = 0; nf < 8; nf++) {
                int n = wn * 64 + nf * 8 + lr;
                bf[nf][0] = __float_as_uint(Bc[n * 36 + kk + lc]);
                bf[nf][1] = __float_as_uint(Bc[n * 36 + kk + lc + 4]);
            }
            #pragma unroll
            for (int mf = 0; mf < 4; mf++)
                #pragma unroll
                for (int nf = 0; nf < 8; nf++)
                    mma_tf32(acc[mf][nf], af[mf], bf[nf]);
        }
        __syncthreads();
    }

    #pragma unroll
    for (int mf = 0; mf < 4; mf++) {
        int r = m0 + wm * 64 + mf * 16 + lr;
        #pragma unroll
        for (int nf = 0; nf < 8; nf++) {
            int c = n0 + wn * 64 + nf * 8 + 2 * lc;
            float b0 = 0.0f, b1 = 0.0f;
            if (bias) { b0 = bias[c]; b1 = bias[c + 1]; }
            float o00 = acc[mf][nf][0] + b0, o01 = acc[mf][nf][1] + b1;
            float o10 = acc[mf][nf][2] + b0, o11 = acc[mf][nf][3] + b1;
            if (round_out) {
                o00 = __uint_as_float(f2tf32(o00)); o01 = __uint_as_float(f2tf32(o01));
                o10 = __uint_as_float(f2tf32(o10)); o11 = __uint_as_float(f2tf32(o11));
            }
            float2 v0 = { o00, o01 };
            float2 v1 = { o10, o11 };
            *(float2*)&C[(size_t)r * N + c] = v0;
            *(float2*)&C[(size_t)(r + 8) * N + c] = v1;
        }
    }
}

// ======================================================================
// Flash attention v3, tf32. 128-row q tile, 4 warps, warp = 32 q x 64 keys.
// Pair-interleaved smem for Q/K/P: within each 8-col group, col j stored at
// 2j (j<4) or 2j-7 (j>=4), so fragment pairs (j, j+4) are adjacent -> LDS.64.
// Inputs pre-rounded to tf32 -> no cvt except on exp'd P. Output rounded.
// smem (floats/u32, stride 72): qs 128x72 @0, ks 64x72 @9216, vs @13824,
//                               ps 128x72 @18432 -> 27648 = 110,592 B
// ======================================================================
#define FL_SMEM_BYTES (27648 * 4)

__global__ __launch_bounds__(128) void flash_tf32_v3(
    const float* __restrict__ Q, const float* __restrict__ Kp,
    const float* __restrict__ Vp, float* __restrict__ O)
{
    extern __shared__ float smf[];
    uint32_t* qs = (uint32_t*)smf;
    uint32_t* ks = (uint32_t*)(smf + 9216);
    uint32_t* vs = (uint32_t*)(smf + 13824);
    uint32_t* ps = (uint32_t*)(smf + 18432);

    const int tid  = threadIdx.x;
    const int lane = tid & 31;
    const int w    = tid >> 5;      // 0..3: 32 q-rows each
    const int lr   = lane >> 2;
    const int lc   = lane & 3;

    const int bh = blockIdx.y;
    const int b  = bh >> 4;
    const int h  = bh & 15;
    const int q0 = blockIdx.x * 128;
    const float scale = 0.03125f;   // 1/sqrt(1024), exact power of 2

    const int fr = tid >> 4;          // 0..7
    const int fc = (tid & 15) * 4;    // 0..60
    const int ibase = (fc & ~7) + ((fc & 4) ? 1 : 0);   // interleave store base

    // ---- load Q tile (128 x 64): scale (exact), interleaved scatter ----
    const float* qbase = Q + ((size_t)(b * SS + q0)) * DD + h * HD;
    #pragma unroll
    for (int i = 0; i < 16; i++) {
        int r = fr + i * 8;
        float4 v = *(const float4*)&qbase[(size_t)r * DD + fc];
        uint32_t* dst = &qs[r * 72 + ibase];
        dst[0] = __float_as_uint(v.x * scale);
        dst[2] = __float_as_uint(v.y * scale);
        dst[4] = __float_as_uint(v.z * scale);
        dst[6] = __float_as_uint(v.w * scale);
    }

    float m_state[2][2], l_state[2][2];
    float acco[2][8][4];
    #pragma unroll
    for (int mf = 0; mf < 2; mf++)
        #pragma unroll
        for (int hh = 0; hh < 2; hh++) { m_state[mf][hh] = -INFINITY; l_state[mf][hh] = 0.0f; }
    #pragma unroll
    for (int mf = 0; mf < 2; mf++)
        #pragma unroll
        for (int nf = 0; nf < 8; nf++)
            #pragma unroll
            for (int t = 0; t < 4; t++) acco[mf][nf][t] = 0.0f;

    // prefetch K/V tile 0 into regs
    const float* kb0 = Kp + ((size_t)(b * SS)) * DD + h * HD;
    const float* vb0 = Vp + ((size_t)(b * SS)) * DD + h * HD;
    float4 kreg[8], vreg[8];
    #pragma unroll
    for (int i = 0; i < 8; i++) {
        int r = fr + i * 8;
        kreg[i] = *(const float4*)&kb0[(size_t)r * DD + fc];
        vreg[i] = *(const float4*)&vb0[(size_t)r * DD + fc];
    }

    for (int kb = 0; kb < SS / 64; kb++) {
        __syncthreads();   // previous tile fully consumed
        #pragma unroll
        for (int i = 0; i < 8; i++) {
            int r = fr + i * 8;
            // K: interleaved scatter (no cvt, pre-rounded)
            uint32_t* kdst = &ks[r * 72 + ibase];
            kdst[0] = __float_as_uint(kreg[i].x);
            kdst[2] = __float_as_uint(kreg[i].y);
            kdst[4] = __float_as_uint(kreg[i].z);
            kdst[6] = __float_as_uint(kreg[i].w);
            // V: plain vector store
            uint4 uv = { __float_as_uint(vreg[i].x), __float_as_uint(vreg[i].y),
                         __float_as_uint(vreg[i].z), __float_as_uint(vreg[i].w) };
            *(uint4*)&vs[r * 72 + fc] = uv;
        }
        __syncthreads();   // tile visible

        // prefetch next tile (overlaps compute)
        if (kb + 1 < SS / 64) {
            const float* kbn = Kp + ((size_t)(b * SS + (kb + 1) * 64)) * DD + h * HD;
            const float* vbn = Vp + ((size_t)(b * SS + (kb + 1) * 64)) * DD + h * HD;
            #pragma unroll
            for (int i = 0; i < 8; i++) {
                int r = fr + i * 8;
                kreg[i] = *(const float4*)&kbn[(size_t)r * DD + fc];
                vreg[i] = *(const float4*)&vbn[(size_t)r * DD + fc];
            }
        }

        // ---- S = Q K^T : warp tile 32 q x 64 keys ----
        float accs[2][8][4];
        #pragma unroll
        for (int mf = 0; mf < 2; mf++)
            #pragma unroll
            for (int nf = 0; nf < 8; nf++)
                #pragma unroll
                for (int t = 0; t < 4; t++) accs[mf][nf][t] = 0.0f;

        #pragma unroll
        for (int ksi = 0; ksi < 8; ksi++) {
            const int kk = ksi * 8;
            uint32_t af[2][4];
            #pragma unroll
            for (int mf = 0; mf < 2; mf++) {
                int r = w * 32 + mf * 16 + lr;
                uint2 u0 = *(const uint2*)&qs[r * 72 + kk + 2 * lc];         // (a0,a2)
                uint2 u1 = *(const uint2*)&qs[(r + 8) * 72 + kk + 2 * lc];   // (a1,a3)
                af[mf][0] = u0.x; af[mf][1] = u1.x; af[mf][2] = u0.y; af[mf][3] = u1.y;
            }
            uint32_t bf[8][2];
            #pragma unroll
            for (int nf = 0; nf < 8; nf++) {
                int n = nf * 8 + lr;
                uint2 v = *(const uint2*)&ks[n * 72 + kk + 2 * lc];          // (b0,b1)
                bf[nf][0] = v.x; bf[nf][1] = v.y;
            }
            #pragma unroll
            for (int mf = 0; mf < 2; mf++)
                #pragma unroll
                for (int nf = 0; nf < 8; nf++)
                    mma_tf32(accs[mf][nf], af[mf], bf[nf]);
        }

        // ---- warp-local online softmax ----
        float cc[2][2];
        #pragma unroll
        for (int mf = 0; mf < 2; mf++)
            #pragma unroll
            for (int hh = 0; hh < 2; hh++) {
                float v = -INFINITY;
                #pragma unroll
                for (int nf = 0; nf < 8; nf++) {
                    v = fmaxf(v, accs[mf][nf][2 * hh]);
                    v = fmaxf(v, accs[mf][nf][2 * hh + 1]);
                }
                v = fmaxf(v, __shfl_xor_sync(0xffffffffu, v, 1));
                v = fmaxf(v, __shfl_xor_sync(0xffffffffu, v, 2));
                float mnew = fmaxf(m_state[mf][hh], v);
                cc[mf][hh] = __expf(m_state[mf][hh] - mnew);
                m_state[mf][hh] = mnew;
            }

        // interleaved P column offsets: col 2lc -> e0, col 2lc+1 -> e0+2
        const int e0 = (lc < 2) ? 4 * lc : 4 * lc - 7;

        float rsum[2][2] = {};
        #pragma unroll
        for (int mf = 0; mf < 2; mf++) {
            #pragma unroll
            for (int nf = 0; nf < 8; nf++) {
                float p0 = __expf(accs[mf][nf][0] - m_state[mf][0]);
                float p1 = __expf(accs[mf][nf][1] - m_state[mf][0]);
                float p2 = __expf(accs[mf][nf][2] - m_state[mf][1]);
                float p3 = __expf(accs[mf][nf][3] - m_state[mf][1]);
                rsum[mf][0] += p0 + p1;
                rsum[mf][1] += p2 + p3;
                int r = w * 32 + mf * 16 + lr;
                uint32_t* d0 = &ps[r * 72 + nf * 8 + e0];
                uint32_t* d1 = &ps[(r + 8) * 72 + nf * 8 + e0];
                d0[0] = f2tf32(p0); d0[2] = f2tf32(p1);
                d1[0] = f2tf32(p2); d1[2] = f2tf32(p3);
            }
        }
        #pragma unroll
        for (int mf = 0; mf < 2; mf++)
            #pragma unroll
            for (int hh = 0; hh < 2; hh++) {
                float v = rsum[mf][hh];
                v += __shfl_xor_sync(0xffffffffu, v, 1);
                v += __shfl_xor_sync(0xffffffffu, v, 2);
                l_state[mf][hh] = l_state[mf][hh] * cc[mf][hh] + v;
            }

        // rescale O accumulators
        #pragma unroll
        for (int mf = 0; mf < 2; mf++)
            #pragma unroll
            for (int nf = 0; nf < 8; nf++) {
                acco[mf][nf][0] *= cc[mf][0];
                acco[mf][nf][1] *= cc[mf][0];
                acco[mf][nf][2] *= cc[mf][1];
                acco[mf][nf][3] *= cc[mf][1];
            }

        __syncwarp();   // order P stores before cross-lane P fragment loads

        // ---- O += P V : warp tile 32 q x 64 dims, k = 64 keys ----
        #pragma unroll
        for (int ksi = 0; ksi < 8; ksi++) {
            const int kk = ksi * 8;
            uint32_t af[2][4];
            #pragma unroll
            for (int mf = 0; mf < 2; mf++) {
                int r = w * 32 + mf * 16 + lr;
                uint2 u0 = *(const uint2*)&ps[r * 72 + kk + 2 * lc];
                uint2 u1 = *(const uint2*)&ps[(r + 8) * 72 + kk + 2 * lc];
                af[mf][0] = u0.x; af[mf][1] = u1.x; af[mf][2] = u0.y; af[mf][3] = u1.y;
            }
            uint32_t bf[8][2];
            #pragma unroll
            for (int nf = 0; nf < 8; nf++) {
                int n = nf * 8 + lr;
                bf[nf][0] = vs[(kk + lc) * 72 + n];
                bf[nf][1] = vs[(kk + lc + 4) * 72 + n];
            }
            #pragma unroll
            for (int mf = 0; mf < 2; mf++)
                #pragma unroll
                for (int nf = 0; nf < 8; nf++)
                    mma_tf32(acco[mf][nf], af[mf], bf[nf]);
        }
    }

    // ---- epilogue: normalize, tf32-round (next gemm reads raw bits) ----
    float* obase = O + ((size_t)(b * SS + q0)) * DD + h * HD;
    #pragma unroll
    for (int mf = 0; mf < 2; mf++) {
        float inv0 = 1.0f / l_state[mf][0];
        float inv1 = 1.0f / l_state[mf][1];
        int r = w * 32 + mf * 16 + lr;
        #pragma unroll
        for (int nf = 0; nf < 8; nf++) {
            int c = nf * 8 + 2 * lc;
            uint2 v0 = { f2tf32(acco[mf][nf][0] * inv0), f2tf32(acco[mf][nf][1] * inv0) };
            uint2 v1 = { f2tf32(acco[mf][nf][2] * inv1), f2tf32(acco[mf][nf][3] * inv1) };
            *(uint2*)&obase[(size_t)r * DD + c] = v0;
            *(uint2*)&obase[(size_t)(r + 8) * DD + c] = v1;
        }
    }
}

// ======================================================================
// launch
// ======================================================================
extern "C" void kernel_launch(void* const* d_in, const int* in_sizes, int n_in,
                              void* d_out, int out_size)
{
    const float* queries = (const float*)d_in[0];
    const float* keys    = (const float*)d_in[1];
    const float* values  = (const float*)d_in[2];
    const float* Wq      = (const float*)d_in[3];
    const float* Wk      = (const float*)d_in[4];
    const float* Wv      = (const float*)d_in[5];
    const float* Wo      = (const float*)d_in[6];
    const float* bo      = (const float*)d_in[7];
    float* out = (float*)d_out;

    float *gQ, *gK, *gV, *gA, *gqc, *gkc, *gvc, *gwq, *gwk, *gwv, *gwo;
    cudaGetSymbolAddress((void**)&gQ, g_Q);
    cudaGetSymbolAddress((void**)&gK, g_K);
    cudaGetSymbolAddress((void**)&gV, g_V);
    cudaGetSymbolAddress((void**)&gA, g_att);
    cudaGetSymbolAddress((void**)&gqc, g_qc);
    cudaGetSymbolAddress((void**)&gkc, g_kc);
    cudaGetSymbolAddress((void**)&gvc, g_vc);
    cudaGetSymbolAddress((void**)&gwq, g_Wq);
    cudaGetSymbolAddress((void**)&gwk, g_Wk);
    cudaGetSymbolAddress((void**)&gwv, g_Wv);
    cudaGetSymbolAddress((void**)&gwo, g_Wo);

    cudaFuncSetAttribute(gemm_tf32_v3,
                         cudaFuncAttributeMaxDynamicSharedMemorySize, G_SMEM_BYTES);
    cudaFuncSetAttribute(flash_tf32_v3,
                         cudaFuncAttributeMaxDynamicSharedMemorySize, FL_SMEM_BYTES);

    const int M = BB * SS;   // 4096
    const int N = DD;        // 1024
    const int K = DD;        // 1024
    const int NELEM = BB * SS * DD;       // 4M
    const int WELEM = DD * DD;            // 1M

    // tf32-round inputs + weights once
    cvt_tf32_kernel<<<NELEM / 1024, 256>>>(queries, gqc, NELEM / 4);
    cvt_tf32_kernel<<<NELEM / 1024, 256>>>(keys,    gkc, NELEM / 4);
    cvt_tf32_kernel<<<NELEM / 1024, 256>>>(values,  gvc, NELEM / 4);
    cvt_tf32_kernel<<<WELEM / 1024, 256>>>(Wq, gwq, WELEM / 4);
    cvt_tf32_kernel<<<WELEM / 1024, 256>>>(Wk, gwk, WELEM / 4);
    cvt_tf32_kernel<<<WELEM / 1024, 256>>>(Wv, gwv, WELEM / 4);
    cvt_tf32_kernel<<<WELEM / 1024, 256>>>(Wo, gwo, WELEM / 4);

    dim3 gemm_grid(N / 256, M / 128);   // (4, 32) = 128 blocks
    dim3 gemm_block(256);

    gemm_tf32_v3<<<gemm_grid, gemm_block, G_SMEM_BYTES>>>(gqc, gwq, nullptr, gQ, M, N, K, 1);
    gemm_tf32_v3<<<gemm_grid, gemm_block, G_SMEM_BYTES>>>(gkc, gwk, nullptr, gK, M, N, K, 1);
    gemm_tf32_v3<<<gemm_grid, gemm_block, G_SMEM_BYTES>>>(gvc, gwv, nullptr, gV, M, N, K, 1);

    dim3 fl_grid(SS / 128, BB * HH);    // (16, 32) = 512 blocks
    flash_tf32_v3<<<fl_grid, 128, FL_SMEM_BYTES>>>(gQ, gK, gV, gA);

    gemm_tf32_v3<<<gemm_grid, gemm_block, G_SMEM_BYTES>>>(gA, gwo, bo, out, M, N, K, 0);
}

// round 9
// speedup vs baseline: 1.0817x; 1.0817x over previous
#include <cuda_runtime.h>
#include <math.h>
#include <stdint.h>

#define BB 2
#define SS 2048
#define DD 1024
#define HH 16
#define HD 64

// -------- scratch (allocation-free: __device__ globals) --------
__device__ float g_Q[BB*SS*DD];
__device__ float g_K[BB*SS*DD];
__device__ float g_V[BB*SS*DD];
__device__ float g_att[BB*SS*DD];

// -------- helpers --------
__device__ __forceinline__ uint32_t f2tf32(float x) {
    uint32_t r;
    asm("cvt.rna.tf32.f32 %0, %1;" : "=r"(r) : "f"(x));
    return r;
}

__device__ __forceinline__ void mma_tf32(float* d, const uint32_t* a, const uint32_t* b) {
    asm volatile(
        "mma.sync.aligned.m16n8k8.row.col.f32.tf32.tf32.f32 "
        "{%0,%1,%2,%3},{%4,%5,%6,%7},{%8,%9},{%0,%1,%2,%3};"
        : "+f"(d[0]), "+f"(d[1]), "+f"(d[2]), "+f"(d[3])
        : "r"(a[0]), "r"(a[1]), "r"(a[2]), "r"(a[3]), "r"(b[0]), "r"(b[1]));
}

__device__ __forceinline__ void cp_async16(uint32_t smem_addr, const void* gptr) {
    asm volatile("cp.async.cg.shared.global [%0], [%1], 16;"
                 :: "r"(smem_addr), "l"(gptr));
}
__device__ __forceinline__ void cp_commit() {
    asm volatile("cp.async.commit_group;");
}
template <int N>
__device__ __forceinline__ void cp_wait() {
    asm volatile("cp.async.wait_group %0;" :: "n"(N));
}

// ======================================================================
// GEMM: C[M,N] = A[M,K] * B[N,K]^T (+ bias), tf32 mma.sync.
// block 128M x 256N, 256 threads (8 warps, 2Mx4N), warp tile 64x64, KT=32
// 3-stage cp.async pipeline. round_out: tf32-round outputs (scratch).
// smem: As 3x128x36 + Bs 3x256x36 floats = 165,888 B
// ======================================================================
#define G_STG 3
#define G_SMEM_BYTES ((G_STG*128*36 + G_STG*256*36) * 4)

__device__ __forceinline__ void gemm_body(
    const float* __restrict__ A, const float* __restrict__ Bw,
    const float* __restrict__ bias, float* __restrict__ C, int round_out)
{
    extern __shared__ float gsm[];
    float* As = gsm;                     // [3][128*36]
    float* Bs = gsm + G_STG * 128 * 36;  // [3][256*36]

    const int tid  = threadIdx.x;
    const int lane = tid & 31;
    const int w    = tid >> 5;
    const int wm   = w & 1;
    const int wn   = w >> 1;
    const int lr   = lane >> 2;
    const int lc   = lane & 3;

    const int m0 = blockIdx.y * 128;
    const int n0 = blockIdx.x * 256;
    const int K = 1024, N = 1024;

    const uint32_t as_base = (uint32_t)__cvta_generic_to_shared(As);
    const uint32_t bs_base = (uint32_t)__cvta_generic_to_shared(Bs);

    auto load_stage = [&](int s, int kt) {
        const int k0 = kt * 32;
        #pragma unroll
        for (int i = 0; i < 4; i++) {
            int id = tid + i * 256;
            int r = id >> 3, c = (id & 7) * 4;
            cp_async16(as_base + (s * 128 * 36 + r * 36 + c) * 4,
                       &A[(size_t)(m0 + r) * K + k0 + c]);
        }
        #pragma unroll
        for (int i = 0; i < 8; i++) {
            int id = tid + i * 256;
            int r = id >> 3, c = (id & 7) * 4;
            cp_async16(bs_base + (s * 256 * 36 + r * 36 + c) * 4,
                       &Bw[(size_t)(n0 + r) * K + k0 + c]);
        }
        cp_commit();
    };

    float acc[4][8][4];
    #pragma unroll
    for (int i = 0; i < 4; i++)
        #pragma unroll
        for (int j = 0; j < 8; j++)
            #pragma unroll
            for (int t = 0; t < 4; t++) acc[i][j][t] = 0.0f;

    load_stage(0, 0);
    load_stage(1, 1);

    for (int kt = 0; kt < 32; kt++) {
        if (kt == 31) { cp_wait<0>(); } else { cp_wait<1>(); }
        __syncthreads();
        if (kt + 2 < 32) load_stage((kt + 2) % G_STG, kt + 2);

        const int st = kt % G_STG;
        const float* Ac = As + st * 128 * 36;
        const float* Bc = Bs + st * 256 * 36;

        #pragma unroll
        for (int ks = 0; ks < 4; ks++) {
            const int kk = ks * 8;
            uint32_t af[4][4];
            #pragma unroll
            for (int mf = 0; mf < 4; mf++) {
                int r = wm * 64 + mf * 16 + lr;
                af[mf][0] = f2tf32(Ac[r * 36 + kk + lc]);
                af[mf][1] = f2tf32(Ac[(r + 8) * 36 + kk + lc]);
                af[mf][2] = f2tf32(Ac[r * 36 + kk + lc + 4]);
                af[mf][3] = f2tf32(Ac[(r + 8) * 36 + kk + lc + 4]);
            }
            uint32_t bf[8][2];
            #pragma unroll
            for (int nf = 0; nf < 8; nf++) {
                int n = wn * 64 + nf * 8 + lr;
                bf[nf][0] = f2tf32(Bc[n * 36 + kk + lc]);
                bf[nf][1] = f2tf32(Bc[n * 36 + kk + lc + 4]);
            }
            #pragma unroll
            for (int mf = 0; mf < 4; mf++)
                #pragma unroll
                for (int nf = 0; nf < 8; nf++)
                    mma_tf32(acc[mf][nf], af[mf], bf[nf]);
        }
    }

    #pragma unroll
    for (int mf = 0; mf < 4; mf++) {
        int r = m0 + wm * 64 + mf * 16 + lr;
        #pragma unroll
        for (int nf = 0; nf < 8; nf++) {
            int c = n0 + wn * 64 + nf * 8 + 2 * lc;
            float b0 = 0.0f, b1 = 0.0f;
            if (bias) { b0 = bias[c]; b1 = bias[c + 1]; }
            float o00 = acc[mf][nf][0] + b0, o01 = acc[mf][nf][1] + b1;
            float o10 = acc[mf][nf][2] + b0, o11 = acc[mf][nf][3] + b1;
            if (round_out) {
                o00 = __uint_as_float(f2tf32(o00)); o01 = __uint_as_float(f2tf32(o01));
                o10 = __uint_as_float(f2tf32(o10)); o11 = __uint_as_float(f2tf32(o11));
            }
            float2 v0 = { o00, o01 };
            float2 v1 = { o10, o11 };
            *(float2*)&C[(size_t)r * N + c] = v0;
            *(float2*)&C[(size_t)(r + 8) * N + c] = v1;
        }
    }
}

// fused QKV: z selects (input, weight, output); outputs tf32-rounded
__global__ __launch_bounds__(256) void gemm_qkv(
    const float* __restrict__ Xq, const float* __restrict__ Xk,
    const float* __restrict__ Xv,
    const float* __restrict__ Wq, const float* __restrict__ Wk,
    const float* __restrict__ Wv,
    float* __restrict__ Oq, float* __restrict__ Ok, float* __restrict__ Ov)
{
    const int z = blockIdx.z;
    const float* A  = (z == 0) ? Xq : (z == 1) ? Xk : Xv;
    const float* Bw = (z == 0) ? Wq : (z == 1) ? Wk : Wv;
    float*       C  = (z == 0) ? Oq : (z == 1) ? Ok : Ov;
    gemm_body(A, Bw, nullptr, C, 1);
}

__global__ __launch_bounds__(256) void gemm_out(
    const float* __restrict__ A, const float* __restrict__ Bw,
    const float* __restrict__ bias, float* __restrict__ C)
{
    gemm_body(A, Bw, bias, C, 0);
}

// ======================================================================
// Flash attention, tf32 mma.sync. 128-row q tile, 4 warps,
// warp = 32 q x 64 keys, warp-local online softmax, 2 syncs/tile.
// smem stride 68 (banks 4*lr+lc -> conflict-free Q/K/P fragment loads).
// Inputs (Q/K/V scratch) pre-rounded tf32 by gemm epilogue -> no cvt here.
// layout (floats): qs 128x68 @0, ks 64x68 @8704, vs @13056, ps 128x68 @17408
// total 26112 floats = 104,448 B
// ======================================================================
#define FL_STR 68
#define FL_SMEM_BYTES (26112 * 4)

__global__ __launch_bounds__(128) void flash_tf32_v4(
    const float* __restrict__ Q, const float* __restrict__ Kp,
    const float* __restrict__ Vp, float* __restrict__ O)
{
    extern __shared__ float smf[];
    uint32_t* qs = (uint32_t*)smf;
    uint32_t* ks = (uint32_t*)(smf + 8704);
    uint32_t* vs = (uint32_t*)(smf + 13056);
    uint32_t* ps = (uint32_t*)(smf + 17408);

    const int tid  = threadIdx.x;
    const int lane = tid & 31;
    const int w    = tid >> 5;
    const int lr   = lane >> 2;
    const int lc   = lane & 3;

    const int bh = blockIdx.y;
    const int b  = bh >> 4;
    const int h  = bh & 15;
    const int q0 = blockIdx.x * 128;
    const float scale = 0.03125f;   // 2^-5 exact: commutes with tf32 rounding

    const int fr = tid >> 4;
    const int fc = (tid & 15) * 4;

    const float* qbase = Q + ((size_t)(b * SS + q0)) * DD + h * HD;
    #pragma unroll
    for (int i = 0; i < 16; i++) {
        int r = fr + i * 8;
        float4 v = *(const float4*)&qbase[(size_t)r * DD + fc];
        uint4 u = { __float_as_uint(v.x * scale), __float_as_uint(v.y * scale),
                    __float_as_uint(v.z * scale), __float_as_uint(v.w * scale) };
        *(uint4*)&qs[r * FL_STR + fc] = u;
    }

    float m_state[2][2], l_state[2][2];
    float acco[2][8][4];
    #pragma unroll
    for (int mf = 0; mf < 2; mf++)
        #pragma unroll
        for (int hh = 0; hh < 2; hh++) { m_state[mf][hh] = -INFINITY; l_state[mf][hh] = 0.0f; }
    #pragma unroll
    for (int mf = 0; mf < 2; mf++)
        #pragma unroll
        for (int nf = 0; nf < 8; nf++)
            #pragma unroll
            for (int t = 0; t < 4; t++) acco[mf][nf][t] = 0.0f;

    const float* kb0 = Kp + ((size_t)(b * SS)) * DD + h * HD;
    const float* vb0 = Vp + ((size_t)(b * SS)) * DD + h * HD;
    float4 kreg[8], vreg[8];
    #pragma unroll
    for (int i = 0; i < 8; i++) {
        int r = fr + i * 8;
        kreg[i] = *(const float4*)&kb0[(size_t)r * DD + fc];
        vreg[i] = *(const float4*)&vb0[(size_t)r * DD + fc];
    }

    for (int kb = 0; kb < SS / 64; kb++) {
        __syncthreads();
        #pragma unroll
        for (int i = 0; i < 8; i++) {
            int r = fr + i * 8;
            uint4 uk = { __float_as_uint(kreg[i].x), __float_as_uint(kreg[i].y),
                         __float_as_uint(kreg[i].z), __float_as_uint(kreg[i].w) };
            uint4 uv = { __float_as_uint(vreg[i].x), __float_as_uint(vreg[i].y),
                         __float_as_uint(vreg[i].z), __float_as_uint(vreg[i].w) };
            *(uint4*)&ks[r * FL_STR + fc] = uk;
            *(uint4*)&vs[r * FL_STR + fc] = uv;
        }
        __syncthreads();

        if (kb + 1 < SS / 64) {
            const float* kbn = Kp + ((size_t)(b * SS + (kb + 1) * 64)) * DD + h * HD;
            const float* vbn = Vp + ((size_t)(b * SS + (kb + 1) * 64)) * DD + h * HD;
            #pragma unroll
            for (int i = 0; i < 8; i++) {
                int r = fr + i * 8;
                kreg[i] = *(const float4*)&kbn[(size_t)r * DD + fc];
                vreg[i] = *(const float4*)&vbn[(size_t)r * DD + fc];
            }
        }

        float accs[2][8][4];
        #pragma unroll
        for (int mf = 0; mf < 2; mf++)
            #pragma unroll
            for (int nf = 0; nf < 8; nf++)
                #pragma unroll
                for (int t = 0; t < 4; t++) accs[mf][nf][t] = 0.0f;

        #pragma unroll
        for (int ksi = 0; ksi < 8; ksi++) {
            const int kk = ksi * 8;
            uint32_t af[2][4];
            #pragma unroll
            for (int mf = 0; mf < 2; mf++) {
                int r = w * 32 + mf * 16 + lr;
                af[mf][0] = qs[r * FL_STR + kk + lc];
                af[mf][1] = qs[(r + 8) * FL_STR + kk + lc];
                af[mf][2] = qs[r * FL_STR + kk + lc + 4];
                af[mf][3] = qs[(r + 8) * FL_STR + kk + lc + 4];
            }
            uint32_t bf[8][2];
            #pragma unroll
            for (int nf = 0; nf < 8; nf++) {
                int n = nf * 8 + lr;
                bf[nf][0] = ks[n * FL_STR + kk + lc];
                bf[nf][1] = ks[n * FL_STR + kk + lc + 4];
            }
            #pragma unroll
            for (int mf = 0; mf < 2; mf++)
                #pragma unroll
                for (int nf = 0; nf < 8; nf++)
                    mma_tf32(accs[mf][nf], af[mf], bf[nf]);
        }

        float cc[2][2];
        #pragma unroll
        for (int mf = 0; mf < 2; mf++)
            #pragma unroll
            for (int hh = 0; hh < 2; hh++) {
                float v = -INFINITY;
                #pragma unroll
                for (int nf = 0; nf < 8; nf++) {
                    v = fmaxf(v, accs[mf][nf][2 * hh]);
                    v = fmaxf(v, accs[mf][nf][2 * hh + 1]);
                }
                v = fmaxf(v, __shfl_xor_sync(0xffffffffu, v, 1));
                v = fmaxf(v, __shfl_xor_sync(0xffffffffu, v, 2));
                float mnew = fmaxf(m_state[mf][hh], v);
                cc[mf][hh] = __expf(m_state[mf][hh] - mnew);
                m_state[mf][hh] = mnew;
            }

        float rsum[2][2] = {};
        #pragma unroll
        for (int mf = 0; mf < 2; mf++) {
            #pragma unroll
            for (int nf = 0; nf < 8; nf++) {
                float p0 = __expf(accs[mf][nf][0] - m_state[mf][0]);
                float p1 = __expf(accs[mf][nf][1] - m_state[mf][0]);
                float p2 = __expf(accs[mf][nf][2] - m_state[mf][1]);
                float p3 = __expf(accs[mf][nf][3] - m_state[mf][1]);
                rsum[mf][0] += p0 + p1;
                rsum[mf][1] += p2 + p3;
                int r = w * 32 + mf * 16 + lr;
                int c = nf * 8 + 2 * lc;
                uint2 u0 = { f2tf32(p0), f2tf32(p1) };
                uint2 u1 = { f2tf32(p2), f2tf32(p3) };
                *(uint2*)&ps[r * FL_STR + c] = u0;
                *(uint2*)&ps[(r + 8) * FL_STR + c] = u1;
            }
        }
        #pragma unroll
        for (int mf = 0; mf < 2; mf++)
            #pragma unroll
            for (int hh = 0; hh < 2; hh++) {
                float v = rsum[mf][hh];
                v += __shfl_xor_sync(0xffffffffu, v, 1);
                v += __shfl_xor_sync(0xffffffffu, v, 2);
                l_state[mf][hh] = l_state[mf][hh] * cc[mf][hh] + v;
            }

        #pragma unroll
        for (int mf = 0; mf < 2; mf++)
            #pragma unroll
            for (int nf = 0; nf < 8; nf++) {
                acco[mf][nf][0] *= cc[mf][0];
                acco[mf][nf][1] *= cc[mf][0];
                acco[mf][nf][2] *= cc[mf][1];
                acco[mf][nf][3] *= cc[mf][1];
            }

        __syncwarp();

        #pragma unroll
        for (int ksi = 0; ksi < 8; ksi++) {
            const int kk = ksi * 8;
            uint32_t af[2][4];
            #pragma unroll
            for (int mf = 0; mf < 2; mf++) {
                int r = w * 32 + mf * 16 + lr;
                af[mf][0] = ps[r * FL_STR + kk + lc];
                af[mf][1] = ps[(r + 8) * FL_STR + kk + lc];
                af[mf][2] = ps[r * FL_STR + kk + lc + 4];
                af[mf][3] = ps[(r + 8) * FL_STR + kk + lc + 4];
            }
            uint32_t bf[8][2];
            #pragma unroll
            for (int nf = 0; nf < 8; nf++) {
                int n = nf * 8 + lr;
                bf[nf][0] = vs[(kk + lc) * FL_STR + n];
                bf[nf][1] = vs[(kk + lc + 4) * FL_STR + n];
            }
            #pragma unroll
            for (int mf = 0; mf < 2; mf++)
                #pragma unroll
                for (int nf = 0; nf < 8; nf++)
                    mma_tf32(acco[mf][nf], af[mf], bf[nf]);
        }
    }

    float* obase = O + ((size_t)(b * SS + q0)) * DD + h * HD;
    #pragma unroll
    for (int mf = 0; mf < 2; mf++) {
        float inv0 = 1.0f / l_state[mf][0];
        float inv1 = 1.0f / l_state[mf][1];
        int r = w * 32 + mf * 16 + lr;
        #pragma unroll
        for (int nf = 0; nf < 8; nf++) {
            int c = nf * 8 + 2 * lc;
            float2 v0 = { acco[mf][nf][0] * inv0, acco[mf][nf][1] * inv0 };
            float2 v1 = { acco[mf][nf][2] * inv1, acco[mf][nf][3] * inv1 };
            *(float2*)&obase[(size_t)r * DD + c] = v0;
            *(float2*)&obase[(size_t)(r + 8) * DD + c] = v1;
        }
    }
}

// ======================================================================
// launch
// ======================================================================
extern "C" void kernel_launch(void* const* d_in, const int* in_sizes, int n_in,
                              void* d_out, int out_size)
{
    const float* queries = (const float*)d_in[0];
    const float* keys    = (const float*)d_in[1];
    const float* values  = (const float*)d_in[2];
    const float* Wq      = (const float*)d_in[3];
    const float* Wk      = (const float*)d_in[4];
    const float* Wv      = (const float*)d_in[5];
    const float* Wo      = (const float*)d_in[6];
    const float* bo      = (const float*)d_in[7];
    float* out = (float*)d_out;

    float *gQ, *gK, *gV, *gA;
    cudaGetSymbolAddress((void**)&gQ, g_Q);
    cudaGetSymbolAddress((void**)&gK, g_K);
    cudaGetSymbolAddress((void**)&gV, g_V);
    cudaGetSymbolAddress((void**)&gA, g_att);

    cudaFuncSetAttribute(gemm_qkv,
                         cudaFuncAttributeMaxDynamicSharedMemorySize, G_SMEM_BYTES);
    cudaFuncSetAttribute(gemm_out,
                         cudaFuncAttributeMaxDynamicSharedMemorySize, G_SMEM_BYTES);
    cudaFuncSetAttribute(flash_tf32_v4,
                         cudaFuncAttributeMaxDynamicSharedMemorySize, FL_SMEM_BYTES);

    dim3 qkv_grid(4, 32, 3);   // 384 CTAs
    dim3 gemm_block(256);
    gemm_qkv<<<qkv_grid, gemm_block, G_SMEM_BYTES>>>(
        queries, keys, values, Wq, Wk, Wv, gQ, gK, gV);

    dim3 fl_grid(SS / 128, BB * HH);
    flash_tf32_v4<<<fl_grid, 128, FL_SMEM_BYTES>>>(gQ, gK, gV, gA);

    dim3 out_grid(4, 32, 1);
    gemm_out<<<out_grid, gemm_block, G_SMEM_BYTES>>>(gA, Wo, bo, out);
}